// round 12
// baseline (speedup 1.0000x reference)
#include <cuda_runtime.h>
#include <math.h>

#define LMAX 20
#define NK   210           // LMAX*(LMAX+1)/2
#define NCOL 400
#define T    256           // threads/block
#define PTS  128           // points/block (2 threads per point)
#define STRIDE 100         // smem row stride (25 f4, odd f4-count -> conflict-free)
#define NM   10            // m values per parity-thread
#define NWARP (T / 32)

__device__ float2 g_AB[NK];     // normalized recurrence coeffs A,B per (l,m)
__device__ float  g_D2[LMAX];   // skip-2 sectoral diagonal coeff per l
__device__ float  g_S[2];       // seeds: Pbar(0,0), and -norm(1,1) (x sx)

// Tables in double precision. Pbar(l,m) = K(l,m)*P(l,m) (Condon-Shortley in P).
__global__ void init_tables() {
    int idx = threadIdx.x;
    if (idx < NK) {
        int l = 0;
        while ((l + 1) * (l + 2) / 2 <= idx) ++l;
        int m = idx - l * (l + 1) / 2;
        double A = 0.0, Bc = 0.0;
        if (l >= m + 1) {
            A = sqrt((double)((2 * l + 1) * (2 * l - 1)) /
                     (double)((l - m) * (l + m)));
            if (l >= m + 2) {
                double r = (double)(2 * l + 1) / (double)(2 * l - 3)
                         * (double)((l - m) * (l - m - 1))
                         / (double)((l + m) * (l + m - 1));
                Bc = (double)(l + m - 1) / (double)(l - m) * sqrt(r);
            }
        }
        g_AB[idx] = make_float2((float)A, (float)Bc);
    }
    if (idx >= 2 && idx < LMAX) {
        int m = idx;
        double r = (double)(2 * m + 1) / (double)(2 * m - 3);
        r /= (double)(2 * m) * (2 * m - 1) * (2 * m - 2) * (2 * m - 3);
        g_D2[m] = (float)((double)((2 * m - 1) * (2 * m - 3)) * sqrt(r));
    }
    if (idx == 0) {
        g_S[0] = (float)sqrt(1.0 / (4.0 * 3.14159265358979323846));
        g_S[1] = (float)(-sqrt(3.0 / (8.0 * 3.14159265358979323846)));
    }
}

// Rows l in [L0,L1); this thread handles m = PAR, PAR+2, ... Emits cols - CBASE.
template<int L0, int L1, int CBASE, int PAR>
__device__ __forceinline__ void compute_rows(
    float* __restrict__ row, const float2* __restrict__ sAB,
    const float* __restrict__ sD2,
    float x, float sx2, float seed,
    const float (&CM)[NM], const float (&SM)[NM],
    float (&Pa)[NM], float (&Pb)[NM])
{
    #pragma unroll
    for (int l = L0; l < L1; ++l) {
        float Pn[NM];
        #pragma unroll
        for (int j = 0; j < NM; ++j) {
            const int m = PAR + 2 * j;
            if (m > l) continue;
            if (m == l) {
                Pn[j] = (j == 0) ? seed : sD2[l] * sx2 * Pb[j - 1];
            } else {
                float2 ab = sAB[l * (l + 1) / 2 + m];   // LDS.64 broadcast
                Pn[j] = fmaf(ab.x * x, Pa[j], -(ab.y * Pb[j]));
            }
        }
        const int base = l * l + l - CBASE;
        #pragma unroll
        for (int j = 0; j < NM; ++j) {
            const int m = PAR + 2 * j;
            if (m > l) continue;
            float t = Pn[j];
            if (m == 0) row[base] = t;
            else { row[base + m] = t * CM[j]; row[base - m] = t * SM[j]; }
        }
        #pragma unroll
        for (int j = 0; j < NM; ++j) {
            const int m = PAR + 2 * j;
            if (m > l) continue;
            Pb[j] = Pa[j]; Pa[j] = Pn[j];
        }
    }
}

// Flat-index float4 writeback: 32 full lanes per LDS.128 + STG.128 step,
// 512B per store instruction, ~4x fewer mem instructions than scalar.
// CBASE and COLS are multiples of 4 (f4-aligned in smem and gmem).
template<int CBASE, int COLS>
__device__ __forceinline__ void writeback(
    const float* __restrict__ sh, float* __restrict__ out,
    int p0, int np, int tid)
{
    constexpr int NF4 = COLS / 4;
    constexpr int SF4 = STRIDE / 4;
    const float4* s4 = reinterpret_cast<const float4*>(sh);
    int total = np * NF4;
    for (int j = tid; j < total; j += T) {
        int r = j / NF4;                 // constexpr divisor -> mul/shift
        int c = j - r * NF4;
        float4 v = s4[r * SF4 + c];
        *reinterpret_cast<float4*>(out + (size_t)(p0 + r) * NCOL + CBASE + 4 * c) = v;
    }
}

__global__ __launch_bounds__(T, 4) void sh_kernel(
    const float* __restrict__ lonlat, float* __restrict__ out, int B)
{
    __shared__ float2 sAB[NK];
    __shared__ float  sD2[LMAX];
    __shared__ float  sS[2];
    extern __shared__ float sh[];

    const int tid = threadIdx.x;
    const int pt  = tid & (PTS - 1);
    const int par = tid >> 7;               // 0: even m, 1: odd m
    const int p0  = blockIdx.x * PTS;
    const int np  = min(PTS, B - p0);

    for (int i = tid; i < NK; i += T) sAB[i] = g_AB[i];
    if (tid < LMAX) sD2[tid] = g_D2[tid];
    if (tid < 2)    sS[tid]  = g_S[tid];
    __syncthreads();

    const bool active = (pt < np);
    float x = 0.f, sx2 = 0.f, seed = 0.f;
    float CM[NM], SM[NM], Pa[NM], Pb[NM];

    if (active) {
        float2 ll = reinterpret_cast<const float2*>(lonlat)[p0 + pt];
        const float d2r = 0.017453292519943295f;
        float phi   = (ll.x + 180.0f) * d2r;
        float theta = (ll.y +  90.0f) * d2r;
        x = cosf(theta);
        float sx = sinf(theta);
        sx2 = sx * sx;
        float s1, c1;
        sincosf(phi, &s1, &c1);
        float c2 = c1 * c1 - s1 * s1;       // cos(2phi)
        float s2 = 2.0f * s1 * c1;          // sin(2phi)
        const float SQ2 = 1.41421356237309505f;
        if (par == 0) { CM[0] = SQ2;      SM[0] = 0.0f;
                        seed = sS[0]; }
        else          { CM[0] = SQ2 * c1; SM[0] = SQ2 * s1;
                        seed = sS[1] * sx; }
        #pragma unroll
        for (int j = 1; j < NM; ++j) {
            CM[j] = CM[j - 1] * c2 - SM[j - 1] * s2;
            SM[j] = SM[j - 1] * c2 + CM[j - 1] * s2;
        }
        #pragma unroll
        for (int j = 0; j < NM; ++j) { Pa[j] = 0.0f; Pb[j] = 0.0f; }
    }

    float* row = sh + pt * STRIDE;

#define COMPUTE(L0, L1, CB)                                                     \
    if (active) {                                                               \
        if (par == 0) compute_rows<L0, L1, CB, 0>(row, sAB, sD2, x, sx2, seed,  \
                                                  CM, SM, Pa, Pb);              \
        else          compute_rows<L0, L1, CB, 1>(row, sAB, sD2, x, sx2, seed,  \
                                                  CM, SM, Pa, Pb);              \
    }

    // chunk 0: l 0..9   cols [0,100)
    COMPUTE(0, 10, 0)
    __syncthreads();
    writeback<0, 100>(sh, out, p0, np, tid);
    __syncthreads();

    // chunk 1: l 10..13 cols [100,196)
    COMPUTE(10, 14, 100)
    __syncthreads();
    writeback<100, 96>(sh, out, p0, np, tid);
    __syncthreads();

    // chunk 2: l 14..15 cols [196,256)
    COMPUTE(14, 16, 196)
    __syncthreads();
    writeback<196, 60>(sh, out, p0, np, tid);
    __syncthreads();

    // chunk 3: l 16..17 cols [256,324)
    COMPUTE(16, 18, 256)
    __syncthreads();
    writeback<256, 68>(sh, out, p0, np, tid);
    __syncthreads();

    // chunk 4: l 18..19 cols [324,400)
    COMPUTE(18, 20, 324)
    __syncthreads();
    writeback<324, 76>(sh, out, p0, np, tid);
#undef COMPUTE
}

extern "C" void kernel_launch(void* const* d_in, const int* in_sizes, int n_in,
                              void* d_out, int out_size)
{
    const float* lonlat = (const float*)d_in[0];
    float* out = (float*)d_out;
    int B = in_sizes[0] / 2;

    size_t smem = (size_t)PTS * STRIDE * sizeof(float);   // 51,200 B dynamic
    cudaFuncSetAttribute(sh_kernel,
                         cudaFuncAttributeMaxDynamicSharedMemorySize, (int)smem);

    init_tables<<<1, 256>>>();
    int grid = (B + PTS - 1) / PTS;
    sh_kernel<<<grid, T, smem>>>(lonlat, out, B);
}

// round 13
// speedup vs baseline: 1.1185x; 1.1185x over previous
#include <cuda_runtime.h>
#include <math.h>

#define LMAX 20
#define NK   210           // LMAX*(LMAX+1)/2
#define NCOL 400
#define T    256           // threads/block
#define PTS  128           // points/block (2 threads per point)
#define STRIDE 101         // smem row stride in floats (odd -> conflict-free STS)
#define NM   10            // m values per parity-thread
#define NWARP (T / 32)

__device__ float2 g_AB[NK];     // normalized recurrence coeffs A,B per (l,m)
__device__ float  g_D2[LMAX];   // skip-2 sectoral diagonal coeff per l
__device__ float  g_S[2];       // seeds: Pbar(0,0), and -norm(1,1) (x sx)

// Tables in double precision. Pbar(l,m) = K(l,m)*P(l,m) (Condon-Shortley in P).
__global__ void init_tables() {
    int idx = threadIdx.x;
    if (idx < NK) {
        int l = 0;
        while ((l + 1) * (l + 2) / 2 <= idx) ++l;
        int m = idx - l * (l + 1) / 2;
        double A = 0.0, Bc = 0.0;
        if (l >= m + 1) {
            A = sqrt((double)((2 * l + 1) * (2 * l - 1)) /
                     (double)((l - m) * (l + m)));
            if (l >= m + 2) {
                double r = (double)(2 * l + 1) / (double)(2 * l - 3)
                         * (double)((l - m) * (l - m - 1))
                         / (double)((l + m) * (l + m - 1));
                Bc = (double)(l + m - 1) / (double)(l - m) * sqrt(r);
            }
        }
        g_AB[idx] = make_float2((float)A, (float)Bc);
    }
    if (idx >= 2 && idx < LMAX) {
        int m = idx;
        double r = (double)(2 * m + 1) / (double)(2 * m - 3);
        r /= (double)(2 * m) * (2 * m - 1) * (2 * m - 2) * (2 * m - 3);
        g_D2[m] = (float)((double)((2 * m - 1) * (2 * m - 3)) * sqrt(r));
    }
    if (idx == 0) {
        g_S[0] = (float)sqrt(1.0 / (4.0 * 3.14159265358979323846));
        g_S[1] = (float)(-sqrt(3.0 / (8.0 * 3.14159265358979323846)));
    }
}

// Rows l in [L0,L1); this thread handles m = PAR, PAR+2, ... Emits cols - CBASE.
template<int L0, int L1, int CBASE, int PAR>
__device__ __forceinline__ void compute_rows(
    float* __restrict__ row, const float2* __restrict__ sAB,
    const float* __restrict__ sD2,
    float x, float sx2, float seed,
    const float (&CM)[NM], const float (&SM)[NM],
    float (&Pa)[NM], float (&Pb)[NM])
{
    #pragma unroll
    for (int l = L0; l < L1; ++l) {
        float Pn[NM];
        #pragma unroll
        for (int j = 0; j < NM; ++j) {
            const int m = PAR + 2 * j;
            if (m > l) continue;
            if (m == l) {
                Pn[j] = (j == 0) ? seed : sD2[l] * sx2 * Pb[j - 1];
            } else {
                float2 ab = sAB[l * (l + 1) / 2 + m];   // LDS.64 broadcast
                Pn[j] = fmaf(ab.x * x, Pa[j], -(ab.y * Pb[j]));
            }
        }
        const int base = l * l + l - CBASE;
        #pragma unroll
        for (int j = 0; j < NM; ++j) {
            const int m = PAR + 2 * j;
            if (m > l) continue;
            float t = Pn[j];
            if (m == 0) row[base] = t;
            else { row[base + m] = t * CM[j]; row[base - m] = t * SM[j]; }
        }
        #pragma unroll
        for (int j = 0; j < NM; ++j) {
            const int m = PAR + 2 * j;
            if (m > l) continue;
            Pb[j] = Pa[j]; Pa[j] = Pn[j];
        }
    }
}

// Row-per-warp writeback: per row, lanes cover 32 consecutive cols per
// unrolled step (immediate offsets, conflict-free LDS, coalesced 128B STG).
template<int CBASE, int COLS>
__device__ __forceinline__ void writeback(
    const float* __restrict__ sh, float* __restrict__ out,
    int p0, int np, int warp, int lane)
{
    constexpr int NFULL = COLS / 32;
    constexpr int REM   = COLS - NFULL * 32;
    for (int r = warp; r < np; r += NWARP) {
        const float* s = sh + r * STRIDE + lane;
        float* d = out + (size_t)(p0 + r) * NCOL + CBASE + lane;
        #pragma unroll
        for (int u = 0; u < NFULL; ++u)
            d[u * 32] = s[u * 32];
        if (REM && lane < REM)
            d[NFULL * 32] = s[NFULL * 32];
    }
}

__global__ __launch_bounds__(T, 4) void sh_kernel(
    const float* __restrict__ lonlat, float* __restrict__ out, int B)
{
    __shared__ float2 sAB[NK];
    __shared__ float  sD2[LMAX];
    __shared__ float  sS[2];
    extern __shared__ float sh[];

    const int tid  = threadIdx.x;
    const int lane = tid & 31;
    const int warp = tid >> 5;
    const int pt   = tid & (PTS - 1);
    const int par  = tid >> 7;               // 0: even m, 1: odd m
    const int p0   = blockIdx.x * PTS;
    const int np   = min(PTS, B - p0);

    for (int i = tid; i < NK; i += T) sAB[i] = g_AB[i];
    if (tid < LMAX) sD2[tid] = g_D2[tid];
    if (tid < 2)    sS[tid]  = g_S[tid];
    __syncthreads();

    const bool active = (pt < np);
    float x = 0.f, sx2 = 0.f, seed = 0.f;
    float CM[NM], SM[NM], Pa[NM], Pb[NM];

    if (active) {
        float2 ll = reinterpret_cast<const float2*>(lonlat)[p0 + pt];
        const float d2r = 0.017453292519943295f;
        float phi   = (ll.x + 180.0f) * d2r;
        float theta = (ll.y +  90.0f) * d2r;
        x = cosf(theta);
        float sx = sinf(theta);
        sx2 = sx * sx;
        float s1, c1;
        sincosf(phi, &s1, &c1);
        float c2 = c1 * c1 - s1 * s1;       // cos(2phi)
        float s2 = 2.0f * s1 * c1;          // sin(2phi)
        const float SQ2 = 1.41421356237309505f;
        if (par == 0) { CM[0] = SQ2;      SM[0] = 0.0f;
                        seed = sS[0]; }
        else          { CM[0] = SQ2 * c1; SM[0] = SQ2 * s1;
                        seed = sS[1] * sx; }
        #pragma unroll
        for (int j = 1; j < NM; ++j) {
            CM[j] = CM[j - 1] * c2 - SM[j - 1] * s2;
            SM[j] = SM[j - 1] * c2 + CM[j - 1] * s2;
        }
        #pragma unroll
        for (int j = 0; j < NM; ++j) { Pa[j] = 0.0f; Pb[j] = 0.0f; }
    }

    float* row = sh + pt * STRIDE;

#define COMPUTE(L0, L1, CB)                                                     \
    if (active) {                                                               \
        if (par == 0) compute_rows<L0, L1, CB, 0>(row, sAB, sD2, x, sx2, seed,  \
                                                  CM, SM, Pa, Pb);              \
        else          compute_rows<L0, L1, CB, 1>(row, sAB, sD2, x, sx2, seed,  \
                                                  CM, SM, Pa, Pb);              \
    }

    // chunk 0: l 0..9   cols [0,100)
    COMPUTE(0, 10, 0)
    __syncthreads();
    writeback<0, 100>(sh, out, p0, np, warp, lane);
    __syncthreads();

    // chunk 1: l 10..13 cols [100,196)
    COMPUTE(10, 14, 100)
    __syncthreads();
    writeback<100, 96>(sh, out, p0, np, warp, lane);
    __syncthreads();

    // chunk 2: l 14..15 cols [196,256)
    COMPUTE(14, 16, 196)
    __syncthreads();
    writeback<196, 60>(sh, out, p0, np, warp, lane);
    __syncthreads();

    // chunk 3: l 16..17 cols [256,324)
    COMPUTE(16, 18, 256)
    __syncthreads();
    writeback<256, 68>(sh, out, p0, np, warp, lane);
    __syncthreads();

    // chunk 4: l 18..19 cols [324,400)
    COMPUTE(18, 20, 324)
    __syncthreads();
    writeback<324, 76>(sh, out, p0, np, warp, lane);
#undef COMPUTE
}

extern "C" void kernel_launch(void* const* d_in, const int* in_sizes, int n_in,
                              void* d_out, int out_size)
{
    const float* lonlat = (const float*)d_in[0];
    float* out = (float*)d_out;
    int B = in_sizes[0] / 2;

    size_t smem = (size_t)PTS * STRIDE * sizeof(float);   // 51,712 B dynamic
    cudaFuncSetAttribute(sh_kernel,
                         cudaFuncAttributeMaxDynamicSharedMemorySize, (int)smem);

    init_tables<<<1, 256>>>();
    int grid = (B + PTS - 1) / PTS;
    sh_kernel<<<grid, T, smem>>>(lonlat, out, B);
}

// round 14
// speedup vs baseline: 1.2330x; 1.1023x over previous
#include <cuda_runtime.h>
#include <math.h>

#define LMAX 20
#define NK   210           // LMAX*(LMAX+1)/2
#define NCOL 400
#define T    256           // threads/block
#define PTS  128           // points/block (2 threads per point)
#define STRIDE 101         // smem row stride in floats (odd -> conflict-free STS)
#define NM   10            // m values per parity-thread
#define NWARP (T / 32)

// ---------------- compile-time tables ----------------
constexpr double csqrt(double x) {
    if (x <= 0.0) return 0.0;
    double scale = 1.0;
    while (x > 4.0)  { x *= 0.25; scale *= 2.0; }
    while (x < 0.25) { x *= 4.0;  scale *= 0.5; }
    double g = 1.0;
    for (int i = 0; i < 48; ++i) g = 0.5 * (g + x / g);
    return g * scale;
}

struct Tables {
    float ax[NK];   // A coeff
    float bx[NK];   // B coeff
    float d2[LMAX]; // skip-2 sectoral diagonal coeff
};

constexpr Tables make_tables() {
    Tables t{};
    for (int l = 0; l < LMAX; ++l) {
        for (int m = 0; m <= l; ++m) {
            int idx = l * (l + 1) / 2 + m;
            double A = 0.0, Bc = 0.0;
            if (l >= m + 1) {
                A = csqrt((double)((2 * l + 1) * (2 * l - 1)) /
                          (double)((l - m) * (l + m)));
                if (l >= m + 2) {
                    double r = (double)(2 * l + 1) / (double)(2 * l - 3)
                             * (double)((l - m) * (l - m - 1))
                             / (double)((l + m) * (l + m - 1));
                    Bc = (double)(l + m - 1) / (double)(l - m) * csqrt(r);
                }
            }
            t.ax[idx] = (float)A;
            t.bx[idx] = (float)Bc;
        }
    }
    for (int m = 2; m < LMAX; ++m) {
        double r = (double)(2 * m + 1) / (double)(2 * m - 3);
        r /= (double)(2 * m) * (2 * m - 1) * (2 * m - 2) * (2 * m - 3);
        t.d2[m] = (float)((double)((2 * m - 1) * (2 * m - 3)) * csqrt(r));
    }
    return t;
}

__device__ const Tables g_tab = make_tables();

// seeds: Pbar(0,0) = sqrt(1/4pi); -norm(1,1) coefficient = -sqrt(3/8pi)
#define SEED0 0.28209479177387814f
#define SEED1 (-0.34549414947133547f)

// Rows l in [L0,L1); this thread handles m = PAR, PAR+2, ... Emits cols - CBASE.
template<int L0, int L1, int CBASE, int PAR>
__device__ __forceinline__ void compute_rows(
    float* __restrict__ row, const float2* __restrict__ sAB,
    const float* __restrict__ sD2,
    float x, float sx2, float seed,
    const float (&CM)[NM], const float (&SM)[NM],
    float (&Pa)[NM], float (&Pb)[NM])
{
    #pragma unroll
    for (int l = L0; l < L1; ++l) {
        float Pn[NM];
        #pragma unroll
        for (int j = 0; j < NM; ++j) {
            const int m = PAR + 2 * j;
            if (m > l) continue;
            if (m == l) {
                Pn[j] = (j == 0) ? seed : sD2[l] * sx2 * Pb[j - 1];
            } else {
                float2 ab = sAB[l * (l + 1) / 2 + m];   // LDS.64 broadcast
                Pn[j] = fmaf(ab.x * x, Pa[j], -(ab.y * Pb[j]));
            }
        }
        const int base = l * l + l - CBASE;
        #pragma unroll
        for (int j = 0; j < NM; ++j) {
            const int m = PAR + 2 * j;
            if (m > l) continue;
            float t = Pn[j];
            if (m == 0) row[base] = t;
            else { row[base + m] = t * CM[j]; row[base - m] = t * SM[j]; }
        }
        #pragma unroll
        for (int j = 0; j < NM; ++j) {
            const int m = PAR + 2 * j;
            if (m > l) continue;
            Pb[j] = Pa[j]; Pa[j] = Pn[j];
        }
    }
}

// Row-per-warp writeback: per row, lanes cover 32 consecutive cols per
// unrolled step (immediate offsets, conflict-free LDS, coalesced 128B STG).
template<int CBASE, int COLS>
__device__ __forceinline__ void writeback(
    const float* __restrict__ sh, float* __restrict__ out,
    int p0, int np, int warp, int lane)
{
    constexpr int NFULL = COLS / 32;
    constexpr int REM   = COLS - NFULL * 32;
    for (int r = warp; r < np; r += NWARP) {
        const float* s = sh + r * STRIDE + lane;
        float* d = out + (size_t)(p0 + r) * NCOL + CBASE + lane;
        #pragma unroll
        for (int u = 0; u < NFULL; ++u)
            d[u * 32] = s[u * 32];
        if (REM && lane < REM)
            d[NFULL * 32] = s[NFULL * 32];
    }
}

__global__ __launch_bounds__(T, 3) void sh_kernel(
    const float* __restrict__ lonlat, float* __restrict__ out, int B)
{
    __shared__ float2 sAB[NK];
    __shared__ float  sD2[LMAX];
    extern __shared__ float sh[];

    const int tid  = threadIdx.x;
    const int lane = tid & 31;
    const int warp = tid >> 5;
    const int pt   = tid & (PTS - 1);
    const int par  = tid >> 7;               // 0: even m, 1: odd m
    const int p0   = blockIdx.x * PTS;
    const int np   = min(PTS, B - p0);

    for (int i = tid; i < NK; i += T)
        sAB[i] = make_float2(g_tab.ax[i], g_tab.bx[i]);
    if (tid < LMAX) sD2[tid] = g_tab.d2[tid];
    __syncthreads();

    const bool active = (pt < np);
    float x = 0.f, sx2 = 0.f, seed = 0.f;
    float CM[NM], SM[NM], Pa[NM], Pb[NM];

    if (active) {
        float2 ll = reinterpret_cast<const float2*>(lonlat)[p0 + pt];
        const float d2r = 0.017453292519943295f;
        float phi   = (ll.x + 180.0f) * d2r;
        float theta = (ll.y +  90.0f) * d2r;
        x = cosf(theta);
        float sx = sinf(theta);
        sx2 = sx * sx;
        float s1, c1;
        sincosf(phi, &s1, &c1);
        float c2 = c1 * c1 - s1 * s1;       // cos(2phi)
        float s2 = 2.0f * s1 * c1;          // sin(2phi)
        const float SQ2 = 1.41421356237309505f;
        if (par == 0) { CM[0] = SQ2;      SM[0] = 0.0f;
                        seed = SEED0; }
        else          { CM[0] = SQ2 * c1; SM[0] = SQ2 * s1;
                        seed = SEED1 * sx; }
        #pragma unroll
        for (int j = 1; j < NM; ++j) {
            CM[j] = CM[j - 1] * c2 - SM[j - 1] * s2;
            SM[j] = SM[j - 1] * c2 + CM[j - 1] * s2;
        }
        #pragma unroll
        for (int j = 0; j < NM; ++j) { Pa[j] = 0.0f; Pb[j] = 0.0f; }
    }

    float* row = sh + pt * STRIDE;

#define COMPUTE(L0, L1, CB)                                                     \
    if (active) {                                                               \
        if (par == 0) compute_rows<L0, L1, CB, 0>(row, sAB, sD2, x, sx2, seed,  \
                                                  CM, SM, Pa, Pb);              \
        else          compute_rows<L0, L1, CB, 1>(row, sAB, sD2, x, sx2, seed,  \
                                                  CM, SM, Pa, Pb);              \
    }

    // chunk 0: l 0..9   cols [0,100)
    COMPUTE(0, 10, 0)
    __syncthreads();
    writeback<0, 100>(sh, out, p0, np, warp, lane);
    __syncthreads();

    // chunk 1: l 10..13 cols [100,196)
    COMPUTE(10, 14, 100)
    __syncthreads();
    writeback<100, 96>(sh, out, p0, np, warp, lane);
    __syncthreads();

    // chunk 2: l 14..15 cols [196,256)
    COMPUTE(14, 16, 196)
    __syncthreads();
    writeback<196, 60>(sh, out, p0, np, warp, lane);
    __syncthreads();

    // chunk 3: l 16..17 cols [256,324)
    COMPUTE(16, 18, 256)
    __syncthreads();
    writeback<256, 68>(sh, out, p0, np, warp, lane);
    __syncthreads();

    // chunk 4: l 18..19 cols [324,400)
    COMPUTE(18, 20, 324)
    __syncthreads();
    writeback<324, 76>(sh, out, p0, np, warp, lane);
#undef COMPUTE
}

extern "C" void kernel_launch(void* const* d_in, const int* in_sizes, int n_in,
                              void* d_out, int out_size)
{
    const float* lonlat = (const float*)d_in[0];
    float* out = (float*)d_out;
    int B = in_sizes[0] / 2;

    size_t smem = (size_t)PTS * STRIDE * sizeof(float);   // 51,712 B dynamic
    cudaFuncSetAttribute(sh_kernel,
                         cudaFuncAttributeMaxDynamicSharedMemorySize, (int)smem);

    int grid = (B + PTS - 1) / PTS;
    sh_kernel<<<grid, T, smem>>>(lonlat, out, B);
}

// round 15
// speedup vs baseline: 1.3609x; 1.1037x over previous
#include <cuda_runtime.h>
#include <math.h>

#define LMAX 20
#define NK   210           // LMAX*(LMAX+1)/2
#define NCOL 400
#define T    256           // threads/block
#define PTS  64            // points/block (4 threads per point)
#define STRIDE 101         // smem row stride in floats (odd -> conflict-free STS)
#define NM   5             // m values per thread (m = par + 4j)
#define NWARP (T / 32)

// ---------------- compile-time tables ----------------
constexpr double csqrt(double x) {
    if (x <= 0.0) return 0.0;
    double scale = 1.0;
    while (x > 4.0)  { x *= 0.25; scale *= 2.0; }
    while (x < 0.25) { x *= 4.0;  scale *= 0.5; }
    double g = 1.0;
    for (int i = 0; i < 48; ++i) g = 0.5 * (g + x / g);
    return g * scale;
}

struct Tables {
    float ax[NK];    // A coeff
    float bx[NK];    // B coeff
    float d4[LMAX];  // skip-4 sectoral diagonal coeff (valid for m>=4)
    float sd[4];     // seeds: Kbar(m,m) coefficient, m=0..3 (times sx^m)
};

constexpr Tables make_tables() {
    Tables t{};
    for (int l = 0; l < LMAX; ++l) {
        for (int m = 0; m <= l; ++m) {
            int idx = l * (l + 1) / 2 + m;
            double A = 0.0, Bc = 0.0;
            if (l >= m + 1) {
                A = csqrt((double)((2 * l + 1) * (2 * l - 1)) /
                          (double)((l - m) * (l + m)));
                if (l >= m + 2) {
                    double r = (double)(2 * l + 1) / (double)(2 * l - 3)
                             * (double)((l - m) * (l - m - 1))
                             / (double)((l + m) * (l + m - 1));
                    Bc = (double)(l + m - 1) / (double)(l - m) * csqrt(r);
                }
            }
            t.ax[idx] = (float)A;
            t.bx[idx] = (float)Bc;
        }
    }
    // skip-4 diagonal: Pbar(m,m) = d4(m) * sx^4 * Pbar(m-4,m-4)
    for (int m = 4; m < LMAX; ++m) {
        double prodOdd = 1.0;
        for (int k = 0; k < 4; ++k) prodOdd *= (double)(2 * m - 1 - 2 * k);
        double prodFact = 1.0;
        for (int k = 0; k < 8; ++k) prodFact *= (double)(2 * m - k);
        t.d4[m] = (float)(prodOdd *
            csqrt((double)(2 * m + 1) / (double)(2 * m - 7) / prodFact));
    }
    // seeds: (-1)^m (2m-1)!! sqrt((2m+1)/(4pi (2m)!))   (sqrt2 lives in CM/SM)
    const double PI = 3.14159265358979323846;
    for (int m = 0; m < 4; ++m) {
        double dfac = 1.0;
        for (int k = 1; k <= 2 * m - 1; k += 2) dfac *= (double)k;
        double fact = 1.0;
        for (int k = 2; k <= 2 * m; ++k) fact *= (double)k;
        double v = dfac * csqrt((double)(2 * m + 1) / (4.0 * PI * fact));
        t.sd[m] = (float)((m & 1) ? -v : v);
    }
    return t;
}

__device__ const Tables g_tab = make_tables();

// Rows l in [L0,L1); this thread handles m = PAR + 4j. Emits cols - CBASE.
template<int L0, int L1, int CBASE, int PAR>
__device__ __forceinline__ void compute_rows(
    float* __restrict__ row, const float2* __restrict__ sAB,
    const float* __restrict__ sD4,
    float x, float sx4, float seed,
    const float (&CM)[NM], const float (&SM)[NM],
    float (&Pa)[NM], float (&Pb)[NM], float& diag)
{
    #pragma unroll
    for (int l = L0; l < L1; ++l) {
        float Pn[NM];
        #pragma unroll
        for (int j = 0; j < NM; ++j) {
            const int m = PAR + 4 * j;
            if (m > l) continue;
            if (m == l) {
                Pn[j] = (j == 0) ? seed : sD4[l] * sx4 * diag;
                diag = Pn[j];
            } else {
                float2 ab = sAB[l * (l + 1) / 2 + m];   // LDS.64 broadcast
                Pn[j] = fmaf(ab.x * x, Pa[j], -(ab.y * Pb[j]));
            }
        }
        const int base = l * l + l - CBASE;
        #pragma unroll
        for (int j = 0; j < NM; ++j) {
            const int m = PAR + 4 * j;
            if (m > l) continue;
            float t = Pn[j];
            if (m == 0) row[base] = t;
            else { row[base + m] = t * CM[j]; row[base - m] = t * SM[j]; }
        }
        #pragma unroll
        for (int j = 0; j < NM; ++j) {
            const int m = PAR + 4 * j;
            if (m > l) continue;
            Pb[j] = Pa[j]; Pa[j] = Pn[j];
        }
    }
}

// Row-per-warp writeback: per row, lanes cover 32 consecutive cols per
// unrolled step (immediate offsets, conflict-free LDS, coalesced 128B STG).
template<int CBASE, int COLS>
__device__ __forceinline__ void writeback(
    const float* __restrict__ sh, float* __restrict__ out,
    int p0, int np, int warp, int lane)
{
    constexpr int NFULL = COLS / 32;
    constexpr int REM   = COLS - NFULL * 32;
    for (int r = warp; r < np; r += NWARP) {
        const float* s = sh + r * STRIDE + lane;
        float* d = out + (size_t)(p0 + r) * NCOL + CBASE + lane;
        #pragma unroll
        for (int u = 0; u < NFULL; ++u)
            d[u * 32] = s[u * 32];
        if (REM && lane < REM)
            d[NFULL * 32] = s[NFULL * 32];
    }
}

__global__ __launch_bounds__(T, 5) void sh_kernel(
    const float* __restrict__ lonlat, float* __restrict__ out, int B)
{
    __shared__ float2 sAB[NK];
    __shared__ float  sD4[LMAX];
    extern __shared__ float sh[];

    const int tid  = threadIdx.x;
    const int lane = tid & 31;
    const int warp = tid >> 5;
    const int pt   = tid & (PTS - 1);
    const int par  = tid >> 6;               // m mod 4 class (warp-uniform)
    const int p0   = blockIdx.x * PTS;
    const int np   = min(PTS, B - p0);

    for (int i = tid; i < NK; i += T)
        sAB[i] = make_float2(g_tab.ax[i], g_tab.bx[i]);
    if (tid < LMAX) sD4[tid] = g_tab.d4[tid];
    __syncthreads();

    const bool active = (pt < np);
    float x = 0.f, sx4 = 0.f, seed = 0.f, diag = 0.f;
    float CM[NM], SM[NM], Pa[NM], Pb[NM];

    if (active) {
        float2 ll = reinterpret_cast<const float2*>(lonlat)[p0 + pt];
        const float d2r = 0.017453292519943295f;
        float phi   = (ll.x + 180.0f) * d2r;
        float theta = (ll.y +  90.0f) * d2r;
        x = cosf(theta);
        float sx = sinf(theta);
        float sx2 = sx * sx;
        sx4 = sx2 * sx2;
        float s1, c1;
        sincosf(phi, &s1, &c1);
        float c2 = c1 * c1 - s1 * s1;       // cos(2phi)
        float s2 = 2.0f * s1 * c1;          // sin(2phi)
        float c4 = c2 * c2 - s2 * s2;       // cos(4phi)
        float s4 = 2.0f * s2 * c2;          // sin(4phi)
        const float SQ2 = 1.41421356237309505f;
        float sxp;
        if (par == 0)      { CM[0] = SQ2;       SM[0] = 0.0f;      sxp = 1.0f; }
        else if (par == 1) { CM[0] = SQ2 * c1;  SM[0] = SQ2 * s1;  sxp = sx; }
        else if (par == 2) { CM[0] = SQ2 * c2;  SM[0] = SQ2 * s2;  sxp = sx2; }
        else               { float c3 = c1 * c2 - s1 * s2;
                             float s3 = s1 * c2 + c1 * s2;
                             CM[0] = SQ2 * c3;  SM[0] = SQ2 * s3;  sxp = sx2 * sx; }
        seed = g_tab.sd[par] * sxp;
        #pragma unroll
        for (int j = 1; j < NM; ++j) {
            CM[j] = CM[j - 1] * c4 - SM[j - 1] * s4;
            SM[j] = SM[j - 1] * c4 + CM[j - 1] * s4;
        }
        #pragma unroll
        for (int j = 0; j < NM; ++j) { Pa[j] = 0.0f; Pb[j] = 0.0f; }
    }

    float* row = sh + pt * STRIDE;

#define COMPUTE(L0, L1, CB)                                                       \
    if (active) {                                                                 \
        if      (par == 0) compute_rows<L0, L1, CB, 0>(row, sAB, sD4, x, sx4,     \
                                     seed, CM, SM, Pa, Pb, diag);                 \
        else if (par == 1) compute_rows<L0, L1, CB, 1>(row, sAB, sD4, x, sx4,     \
                                     seed, CM, SM, Pa, Pb, diag);                 \
        else if (par == 2) compute_rows<L0, L1, CB, 2>(row, sAB, sD4, x, sx4,     \
                                     seed, CM, SM, Pa, Pb, diag);                 \
        else               compute_rows<L0, L1, CB, 3>(row, sAB, sD4, x, sx4,     \
                                     seed, CM, SM, Pa, Pb, diag);                 \
    }

    // chunk 0: l 0..9   cols [0,100)
    COMPUTE(0, 10, 0)
    __syncthreads();
    writeback<0, 100>(sh, out, p0, np, warp, lane);
    __syncthreads();

    // chunk 1: l 10..13 cols [100,196)
    COMPUTE(10, 14, 100)
    __syncthreads();
    writeback<100, 96>(sh, out, p0, np, warp, lane);
    __syncthreads();

    // chunk 2: l 14..15 cols [196,256)
    COMPUTE(14, 16, 196)
    __syncthreads();
    writeback<196, 60>(sh, out, p0, np, warp, lane);
    __syncthreads();

    // chunk 3: l 16..17 cols [256,324)
    COMPUTE(16, 18, 256)
    __syncthreads();
    writeback<256, 68>(sh, out, p0, np, warp, lane);
    __syncthreads();

    // chunk 4: l 18..19 cols [324,400)
    COMPUTE(18, 20, 324)
    __syncthreads();
    writeback<324, 76>(sh, out, p0, np, warp, lane);
#undef COMPUTE
}

extern "C" void kernel_launch(void* const* d_in, const int* in_sizes, int n_in,
                              void* d_out, int out_size)
{
    const float* lonlat = (const float*)d_in[0];
    float* out = (float*)d_out;
    int B = in_sizes[0] / 2;

    size_t smem = (size_t)PTS * STRIDE * sizeof(float);   // 25,856 B dynamic
    cudaFuncSetAttribute(sh_kernel,
                         cudaFuncAttributeMaxDynamicSharedMemorySize, (int)smem);

    int grid = (B + PTS - 1) / PTS;
    sh_kernel<<<grid, T, smem>>>(lonlat, out, B);
}

// round 16
// speedup vs baseline: 1.5503x; 1.1392x over previous
#include <cuda_runtime.h>
#include <math.h>

#define LMAX 20
#define NK   210           // LMAX*(LMAX+1)/2
#define NCOL 400
#define T    256           // threads/block
#define PTS  64            // points/block (4 threads per point)
#define STRIDE 145         // smem row stride in floats (odd -> conflict-free STS)
#define NM   5             // m values per thread (m = par + 4j)
#define NWARP (T / 32)

// ---------------- compile-time tables ----------------
constexpr double csqrt(double x) {
    if (x <= 0.0) return 0.0;
    double scale = 1.0;
    while (x > 4.0)  { x *= 0.25; scale *= 2.0; }
    while (x < 0.25) { x *= 4.0;  scale *= 0.5; }
    double g = 1.0;
    for (int i = 0; i < 48; ++i) g = 0.5 * (g + x / g);
    return g * scale;
}

struct Tables {
    float ax[NK];    // A coeff
    float bx[NK];    // B coeff
    float d4[LMAX];  // skip-4 sectoral diagonal coeff (valid for m>=4)
    float sd[4];     // seeds: Kbar(m,m) coefficient, m=0..3 (times sx^m)
};

constexpr Tables make_tables() {
    Tables t{};
    for (int l = 0; l < LMAX; ++l) {
        for (int m = 0; m <= l; ++m) {
            int idx = l * (l + 1) / 2 + m;
            double A = 0.0, Bc = 0.0;
            if (l >= m + 1) {
                A = csqrt((double)((2 * l + 1) * (2 * l - 1)) /
                          (double)((l - m) * (l + m)));
                if (l >= m + 2) {
                    double r = (double)(2 * l + 1) / (double)(2 * l - 3)
                             * (double)((l - m) * (l - m - 1))
                             / (double)((l + m) * (l + m - 1));
                    Bc = (double)(l + m - 1) / (double)(l - m) * csqrt(r);
                }
            }
            t.ax[idx] = (float)A;
            t.bx[idx] = (float)Bc;
        }
    }
    // skip-4 diagonal: Pbar(m,m) = d4(m) * sx^4 * Pbar(m-4,m-4)
    for (int m = 4; m < LMAX; ++m) {
        double prodOdd = 1.0;
        for (int k = 0; k < 4; ++k) prodOdd *= (double)(2 * m - 1 - 2 * k);
        double prodFact = 1.0;
        for (int k = 0; k < 8; ++k) prodFact *= (double)(2 * m - k);
        t.d4[m] = (float)(prodOdd *
            csqrt((double)(2 * m + 1) / (double)(2 * m - 7) / prodFact));
    }
    // seeds: (-1)^m (2m-1)!! sqrt((2m+1)/(4pi (2m)!))   (sqrt2 lives in CM/SM)
    const double PI = 3.14159265358979323846;
    for (int m = 0; m < 4; ++m) {
        double dfac = 1.0;
        for (int k = 1; k <= 2 * m - 1; k += 2) dfac *= (double)k;
        double fact = 1.0;
        for (int k = 2; k <= 2 * m; ++k) fact *= (double)k;
        double v = dfac * csqrt((double)(2 * m + 1) / (4.0 * PI * fact));
        t.sd[m] = (float)((m & 1) ? -v : v);
    }
    return t;
}

__device__ const Tables g_tab = make_tables();

// Rows l in [L0,L1); this thread handles m = PAR + 4j. Emits cols - CBASE.
template<int L0, int L1, int CBASE, int PAR>
__device__ __forceinline__ void compute_rows(
    float* __restrict__ row, const float2* __restrict__ sAB,
    const float* __restrict__ sD4,
    float x, float sx4, float seed,
    const float (&CM)[NM], const float (&SM)[NM],
    float (&Pa)[NM], float (&Pb)[NM], float& diag)
{
    #pragma unroll
    for (int l = L0; l < L1; ++l) {
        float Pn[NM];
        #pragma unroll
        for (int j = 0; j < NM; ++j) {
            const int m = PAR + 4 * j;
            if (m > l) continue;
            if (m == l) {
                Pn[j] = (j == 0) ? seed : sD4[l] * sx4 * diag;
                diag = Pn[j];
            } else {
                float2 ab = sAB[l * (l + 1) / 2 + m];   // LDS.64 broadcast
                Pn[j] = fmaf(ab.x * x, Pa[j], -(ab.y * Pb[j]));
            }
        }
        const int base = l * l + l - CBASE;
        #pragma unroll
        for (int j = 0; j < NM; ++j) {
            const int m = PAR + 4 * j;
            if (m > l) continue;
            float t = Pn[j];
            if (m == 0) row[base] = t;
            else { row[base + m] = t * CM[j]; row[base - m] = t * SM[j]; }
        }
        #pragma unroll
        for (int j = 0; j < NM; ++j) {
            const int m = PAR + 4 * j;
            if (m > l) continue;
            Pb[j] = Pa[j]; Pa[j] = Pn[j];
        }
    }
}

// Pairwise-interleaved row-per-warp writeback: two rows per iteration,
// loads batched before stores (2x LDS/STG MLP). All chunk bases are
// sector-aligned (CBASE mod 8 == 0) -> every full STG is 4-sector/128B.
template<int CBASE, int COLS>
__device__ __forceinline__ void writeback(
    const float* __restrict__ sh, float* __restrict__ out,
    int p0, int np, int warp, int lane)
{
    constexpr int NFULL = COLS / 32;
    constexpr int REM   = COLS - NFULL * 32;
    int r = warp;
    for (; r + NWARP < np; r += 2 * NWARP) {
        const float* s0 = sh + r * STRIDE + lane;
        const float* s1 = sh + (r + NWARP) * STRIDE + lane;
        float* d0 = out + (size_t)(p0 + r) * NCOL + CBASE + lane;
        float* d1 = out + (size_t)(p0 + r + NWARP) * NCOL + CBASE + lane;
        float v0[NFULL], v1[NFULL];
        #pragma unroll
        for (int u = 0; u < NFULL; ++u) { v0[u] = s0[u * 32]; v1[u] = s1[u * 32]; }
        float t0 = 0.f, t1 = 0.f;
        if (REM && lane < REM) { t0 = s0[NFULL * 32]; t1 = s1[NFULL * 32]; }
        #pragma unroll
        for (int u = 0; u < NFULL; ++u) { d0[u * 32] = v0[u]; d1[u * 32] = v1[u]; }
        if (REM && lane < REM) { d0[NFULL * 32] = t0; d1[NFULL * 32] = t1; }
    }
    for (; r < np; r += NWARP) {
        const float* s = sh + r * STRIDE + lane;
        float* d = out + (size_t)(p0 + r) * NCOL + CBASE + lane;
        #pragma unroll
        for (int u = 0; u < NFULL; ++u)
            d[u * 32] = s[u * 32];
        if (REM && lane < REM)
            d[NFULL * 32] = s[NFULL * 32];
    }
}

__global__ __launch_bounds__(T, 5) void sh_kernel(
    const float* __restrict__ lonlat, float* __restrict__ out, int B)
{
    __shared__ float2 sAB[NK];
    __shared__ float  sD4[LMAX];
    extern __shared__ float sh[];

    const int tid  = threadIdx.x;
    const int lane = tid & 31;
    const int warp = tid >> 5;
    const int pt   = tid & (PTS - 1);
    const int par  = tid >> 6;               // m mod 4 class (warp-uniform)
    const int p0   = blockIdx.x * PTS;
    const int np   = min(PTS, B - p0);

    for (int i = tid; i < NK; i += T)
        sAB[i] = make_float2(g_tab.ax[i], g_tab.bx[i]);
    if (tid < LMAX) sD4[tid] = g_tab.d4[tid];
    __syncthreads();

    const bool active = (pt < np);
    float x = 0.f, sx4 = 0.f, seed = 0.f, diag = 0.f;
    float CM[NM], SM[NM], Pa[NM], Pb[NM];

    if (active) {
        float2 ll = reinterpret_cast<const float2*>(lonlat)[p0 + pt];
        const float d2r = 0.017453292519943295f;
        float phi   = (ll.x + 180.0f) * d2r;
        float theta = (ll.y +  90.0f) * d2r;
        x = cosf(theta);
        float sx = sinf(theta);
        float sx2 = sx * sx;
        sx4 = sx2 * sx2;
        float s1, c1;
        sincosf(phi, &s1, &c1);
        float c2 = c1 * c1 - s1 * s1;       // cos(2phi)
        float s2 = 2.0f * s1 * c1;          // sin(2phi)
        float c4 = c2 * c2 - s2 * s2;       // cos(4phi)
        float s4 = 2.0f * s2 * c2;          // sin(4phi)
        const float SQ2 = 1.41421356237309505f;
        float sxp;
        if (par == 0)      { CM[0] = SQ2;       SM[0] = 0.0f;      sxp = 1.0f; }
        else if (par == 1) { CM[0] = SQ2 * c1;  SM[0] = SQ2 * s1;  sxp = sx; }
        else if (par == 2) { CM[0] = SQ2 * c2;  SM[0] = SQ2 * s2;  sxp = sx2; }
        else               { float c3 = c1 * c2 - s1 * s2;
                             float s3 = s1 * c2 + c1 * s2;
                             CM[0] = SQ2 * c3;  SM[0] = SQ2 * s3;  sxp = sx2 * sx; }
        seed = g_tab.sd[par] * sxp;
        #pragma unroll
        for (int j = 1; j < NM; ++j) {
            CM[j] = CM[j - 1] * c4 - SM[j - 1] * s4;
            SM[j] = SM[j - 1] * c4 + CM[j - 1] * s4;
        }
        #pragma unroll
        for (int j = 0; j < NM; ++j) { Pa[j] = 0.0f; Pb[j] = 0.0f; }
    }

    float* row = sh + pt * STRIDE;

#define COMPUTE(L0, L1, CB)                                                       \
    if (active) {                                                                 \
        if      (par == 0) compute_rows<L0, L1, CB, 0>(row, sAB, sD4, x, sx4,     \
                                     seed, CM, SM, Pa, Pb, diag);                 \
        else if (par == 1) compute_rows<L0, L1, CB, 1>(row, sAB, sD4, x, sx4,     \
                                     seed, CM, SM, Pa, Pb, diag);                 \
        else if (par == 2) compute_rows<L0, L1, CB, 2>(row, sAB, sD4, x, sx4,     \
                                     seed, CM, SM, Pa, Pb, diag);                 \
        else               compute_rows<L0, L1, CB, 3>(row, sAB, sD4, x, sx4,     \
                                     seed, CM, SM, Pa, Pb, diag);                 \
    }

    // chunk 0: l 0..11  cols [0,144)     (144 mod 8 == 0: sector-aligned)
    COMPUTE(0, 12, 0)
    __syncthreads();
    writeback<0, 144>(sh, out, p0, np, warp, lane);
    __syncthreads();

    // chunk 1: l 12..15 cols [144,256)   (256 mod 8 == 0)
    COMPUTE(12, 16, 144)
    __syncthreads();
    writeback<144, 112>(sh, out, p0, np, warp, lane);
    __syncthreads();

    // chunk 2: l 16..19 cols [256,400)
    COMPUTE(16, 20, 256)
    __syncthreads();
    writeback<256, 144>(sh, out, p0, np, warp, lane);
#undef COMPUTE
}

extern "C" void kernel_launch(void* const* d_in, const int* in_sizes, int n_in,
                              void* d_out, int out_size)
{
    const float* lonlat = (const float*)d_in[0];
    float* out = (float*)d_out;
    int B = in_sizes[0] / 2;

    size_t smem = (size_t)PTS * STRIDE * sizeof(float);   // 37,120 B dynamic
    cudaFuncSetAttribute(sh_kernel,
                         cudaFuncAttributeMaxDynamicSharedMemorySize, (int)smem);

    int grid = (B + PTS - 1) / PTS;
    sh_kernel<<<grid, T, smem>>>(lonlat, out, B);
}